// round 3
// baseline (speedup 1.0000x reference)
#include <cuda_runtime.h>

// ---------------------------------------------------------------------------
// QECCEqualModel: 23-qubit statevector gate application + overlap loss.
//
// code0, code1: [2, 2^23] complex (given as separate float re/im arrays)
// unitary:      [23, 2, 2] complex. Gate ind0 acts on bit (22-ind0) of the
//               state index, applying out_d = sum_b a_b * U[b,d]  (i.e. U^T).
// loss = 2 - sum_{p,q} |conj(U code0[p]) . code1[q]|^2
//
// All gates commute (distinct qubits). Two passes:
//   pass1: gates on bits 0..12  (ind0 22..10), contiguous tiles, writes scratch
//   pass2: gates on bits 13..22 (ind0 9..0), gathered tiles, fused dot w/ code1
//   pass3: deterministic reduction of per-block partials -> loss
// ---------------------------------------------------------------------------

#define DIMQ (1u << 23)

__device__ float2 g_scratch[2u * DIMQ];     // 128 MB static scratch (allowed)
__device__ float  g_partials[2048 * 4];     // per-block overlap partials

// out0 = a0*c00 + a1*c10 ; out1 = a0*c01 + a1*c11   (c_bd = U[b][d])
__device__ __forceinline__ void gate_pair(
    float& a0r, float& a0i, float& a1r, float& a1i,
    float c00r, float c00i, float c10r, float c10i,
    float c01r, float c01i, float c11r, float c11i)
{
    float n0r = a0r*c00r - a0i*c00i + a1r*c10r - a1i*c10i;
    float n0i = a0r*c00i + a0i*c00r + a1r*c10i + a1i*c10r;
    float n1r = a0r*c01r - a0i*c01i + a1r*c11r - a1i*c11i;
    float n1i = a0r*c01i + a0i*c01r + a1r*c11i + a1i*c11r;
    a0r = n0r; a0i = n0i; a1r = n1r; a1i = n1i;
}

// Gate across a lane bit via shfl_xor. myb = my bit value.
__device__ __forceinline__ void lane_gate(
    float (&ar)[16], float (&ai)[16], int mask, int myb,
    const float* __restrict__ gur, const float* __restrict__ gui, int ind0)
{
    const int I = ind0 * 4;
    float c00r = gur[I+0], c00i = gui[I+0];
    float c01r = gur[I+1], c01i = gui[I+1];
    float c10r = gur[I+2], c10i = gui[I+2];
    float c11r = gur[I+3], c11i = gui[I+3];
    // myb==0: out0 = me*c00 + other*c10 ; myb==1: out1 = other*c01 + me*c11
    float cmr = myb ? c11r : c00r, cmi = myb ? c11i : c00i;
    float cor = myb ? c01r : c10r, coi = myb ? c01i : c10i;
#pragma unroll
    for (int r = 0; r < 16; ++r) {
        float orr = __shfl_xor_sync(0xffffffffu, ar[r], mask);
        float oii = __shfl_xor_sync(0xffffffffu, ai[r], mask);
        float nr = ar[r]*cmr - ai[r]*cmi + orr*cor - oii*coi;
        float ni = ar[r]*cmi + ai[r]*cmr + orr*coi + oii*cor;
        ar[r] = nr; ai[r] = ni;
    }
}

// Gate across a register bit rb (pairs of the 16 per-thread amplitudes).
__device__ __forceinline__ void reg_gate(
    float (&ar)[16], float (&ai)[16], int rb,
    const float* __restrict__ gur, const float* __restrict__ gui, int ind0)
{
    const int I = ind0 * 4;
    float c00r = gur[I+0], c00i = gui[I+0];
    float c01r = gur[I+1], c01i = gui[I+1];
    float c10r = gur[I+2], c10i = gui[I+2];
    float c11r = gur[I+3], c11i = gui[I+3];
#pragma unroll
    for (int r0 = 0; r0 < 16; ++r0) {
        if (r0 & (1 << rb)) continue;
        int r1 = r0 | (1 << rb);
        gate_pair(ar[r0], ai[r0], ar[r1], ai[r1],
                  c00r, c00i, c10r, c10i, c01r, c01i, c11r, c11i);
    }
}

// ---------------------------------------------------------------------------
// Pass 1: gates on bits 0..12 (ind0 = 22-j for tile bit j). Contiguous tiles
// of 8192 amplitudes. 512 threads x 16 amps in registers.
// mapping1: tileIdx = (r<<9)|(w<<5)|lane  -> lane bits 0..4, warp 5..8, reg 9..12
// mapping2 (after smem restage, swap r<->w): reg covers bits 5..8.
// ---------------------------------------------------------------------------
__global__ void __launch_bounds__(512)
pass1_kernel(const float* __restrict__ c0r, const float* __restrict__ c0i,
             const float* __restrict__ ur,  const float* __restrict__ ui)
{
    __shared__ float gur[92], gui[92];
    extern __shared__ float2 smem_f2[];   // 8192 float2 = 64 KB

    const int tid  = threadIdx.x;
    if (tid < 92) { gur[tid] = ur[tid]; gui[tid] = ui[tid]; }
    __syncthreads();

    const int lane = tid & 31;
    const int w    = tid >> 5;
    const unsigned base = blockIdx.x * 8192u;

    float ar[16], ai[16];
#pragma unroll
    for (int r = 0; r < 16; ++r) {
        unsigned t1 = (unsigned)(r << 9) | (w << 5) | lane;
        ar[r] = c0r[base + t1];
        ai[r] = c0i[base + t1];
    }

    // lane-bit gates: tile bits 0..4 -> ind0 22..18
#pragma unroll
    for (int j = 0; j < 5; ++j)
        lane_gate(ar, ai, 1 << j, (lane >> j) & 1, gur, gui, 22 - j);

    // register gates (mapping1): tile bits 9..12 -> ind0 13..10
#pragma unroll
    for (int rb = 0; rb < 4; ++rb)
        reg_gate(ar, ai, rb, gur, gui, 22 - (9 + rb));

    // restage: swap register bits <-> warp bits
#pragma unroll
    for (int r = 0; r < 16; ++r) {
        unsigned t1 = (unsigned)(r << 9) | (w << 5) | lane;
        smem_f2[t1] = make_float2(ar[r], ai[r]);
    }
    __syncthreads();
#pragma unroll
    for (int r = 0; r < 16; ++r) {
        unsigned t2 = (unsigned)(w << 9) | (r << 5) | lane;
        float2 v = smem_f2[t2];
        ar[r] = v.x; ai[r] = v.y;
    }

    // register gates (mapping2): tile bits 5..8 -> ind0 17..14
#pragma unroll
    for (int rb = 0; rb < 4; ++rb)
        reg_gate(ar, ai, rb, gur, gui, 22 - (5 + rb));

#pragma unroll
    for (int r = 0; r < 16; ++r) {
        unsigned t2 = (unsigned)(w << 9) | (r << 5) | lane;
        g_scratch[base + t2] = make_float2(ar[r], ai[r]);
    }
}

// ---------------------------------------------------------------------------
// Pass 2: gates on bits 13..22 (h bits 0..9, ind0 = 9-hb), fused with the
// overlap dot product against code1. Tile = 2^10 h-combos x 8 contiguous low
// amplitudes (per state p). tileIdx (13b): bits 0..2 = l, bits 3..12 = h.
// Tile bit j (j>=3) = state bit 10+j -> gate ind0 = 12-j.
// mapping1: tileIdx = (r<<9)|(w<<5)|lane  (lane covers l + tile bits 3,4)
//   lane gates: tile bits 3,4 -> ind0 9,8
//   reg gates (mapping1): tile bits 9..12 -> ind0 3..0   (ind0 = 3-rb)
//   restage, reg gates (mapping2): tile bits 5..8 -> ind0 7..4
// ---------------------------------------------------------------------------
__global__ void __launch_bounds__(512)
pass2_kernel(const float* __restrict__ c1r, const float* __restrict__ c1i,
             const float* __restrict__ ur,  const float* __restrict__ ui)
{
    __shared__ float gur[92], gui[92];
    extern __shared__ float2 smem_f2[];   // 8192 float2 = 64 KB

    const int tid  = threadIdx.x;
    if (tid < 92) { gur[tid] = ur[tid]; gui[tid] = ui[tid]; }
    __syncthreads();

    const int lane = tid & 31;
    const int w    = tid >> 5;
    const unsigned b  = blockIdx.x;
    const unsigned p  = b >> 10;            // which code0 state
    const unsigned l0 = (b & 1023u) * 8u;   // low-index block
    const unsigned stateBase = p << 23;

    float ar[16], ai[16];
#pragma unroll
    for (int r = 0; r < 16; ++r) {
        unsigned t1 = (unsigned)(r << 9) | (w << 5) | lane;
        unsigned s  = ((t1 >> 3) << 13) + l0 + (t1 & 7u);
        float2 v = g_scratch[stateBase + s];
        ar[r] = v.x; ai[r] = v.y;
    }

    // lane-bit gates: tile bits 3,4 -> ind0 9,8
    lane_gate(ar, ai, 1 << 3, (lane >> 3) & 1, gur, gui, 9);
    lane_gate(ar, ai, 1 << 4, (lane >> 4) & 1, gur, gui, 8);

    // register gates (mapping1): tile bits 9..12 -> ind0 = 12-(9+rb) = 3-rb
#pragma unroll
    for (int rb = 0; rb < 4; ++rb)
        reg_gate(ar, ai, rb, gur, gui, 3 - rb);

    // restage: swap register bits <-> warp bits
#pragma unroll
    for (int r = 0; r < 16; ++r) {
        unsigned t1 = (unsigned)(r << 9) | (w << 5) | lane;
        smem_f2[t1] = make_float2(ar[r], ai[r]);
    }
    __syncthreads();
#pragma unroll
    for (int r = 0; r < 16; ++r) {
        unsigned t2 = (unsigned)(w << 9) | (r << 5) | lane;
        float2 v = smem_f2[t2];
        ar[r] = v.x; ai[r] = v.y;
    }

    // register gates (mapping2): tile bits 5..8 -> ind0 = 12-(5+rb) = 7-rb
#pragma unroll
    for (int rb = 0; rb < 4; ++rb)
        reg_gate(ar, ai, rb, gur, gui, 12 - (5 + rb));

    // fused dot: acc[q] += conj(d0) * code1[q]
    float acc0 = 0.f, acc1 = 0.f, acc2 = 0.f, acc3 = 0.f;
#pragma unroll
    for (int r = 0; r < 16; ++r) {
        unsigned t2 = (unsigned)(w << 9) | (r << 5) | lane;
        unsigned s  = ((t2 >> 3) << 13) + l0 + (t2 & 7u);
        float dr = ar[r], di = ai[r];
        float xr = __ldg(&c1r[s]),        xi = __ldg(&c1i[s]);
        acc0 += dr*xr + di*xi;  acc1 += dr*xi - di*xr;
        float yr = __ldg(&c1r[DIMQ + s]), yi = __ldg(&c1i[DIMQ + s]);
        acc2 += dr*yr + di*yi;  acc3 += dr*yi - di*yr;
    }

    // deterministic block reduction
#pragma unroll
    for (int o = 16; o > 0; o >>= 1) {
        acc0 += __shfl_xor_sync(0xffffffffu, acc0, o);
        acc1 += __shfl_xor_sync(0xffffffffu, acc1, o);
        acc2 += __shfl_xor_sync(0xffffffffu, acc2, o);
        acc3 += __shfl_xor_sync(0xffffffffu, acc3, o);
    }
    __syncthreads();                   // smem_f2 reuse
    float* red = (float*)smem_f2;      // 16 warps x 4 floats
    if (lane == 0) {
        red[w*4+0] = acc0; red[w*4+1] = acc1;
        red[w*4+2] = acc2; red[w*4+3] = acc3;
    }
    __syncthreads();
    if (tid < 4) {
        float s = 0.f;
#pragma unroll
        for (int k = 0; k < 16; ++k) s += red[k*4 + tid];
        g_partials[b*4 + tid] = s;
    }
}

// ---------------------------------------------------------------------------
// Pass 3: fixed-order reduction of 2048 block partials -> loss scalar.
// ---------------------------------------------------------------------------
__global__ void pass3_kernel(float* __restrict__ out)
{
    __shared__ float sred[256][8];
    const int tid = threadIdx.x;
    float acc[8];
#pragma unroll
    for (int j = 0; j < 8; ++j) acc[j] = 0.f;

    for (int t = tid; t < 1024; t += 256) {
#pragma unroll
        for (int pq = 0; pq < 2; ++pq)
#pragma unroll
            for (int j = 0; j < 4; ++j)
                acc[pq*4 + j] += g_partials[(pq*1024 + t)*4 + j];
    }
#pragma unroll
    for (int j = 0; j < 8; ++j) sred[tid][j] = acc[j];
    __syncthreads();
    for (int off = 128; off > 0; off >>= 1) {
        if (tid < off) {
#pragma unroll
            for (int j = 0; j < 8; ++j) sred[tid][j] += sred[tid + off][j];
        }
        __syncthreads();
    }
    if (tid == 0) {
        float s = 0.f;
#pragma unroll
        for (int j = 0; j < 8; ++j) s += sred[0][j] * sred[0][j];
        out[0] = 2.0f - s;
    }
}

// ---------------------------------------------------------------------------
extern "C" void kernel_launch(void* const* d_in, const int* in_sizes, int n_in,
                              void* d_out, int out_size)
{
    (void)in_sizes; (void)n_in; (void)out_size;
    const float* c0r = (const float*)d_in[0];
    const float* c0i = (const float*)d_in[1];
    const float* c1r = (const float*)d_in[2];
    const float* c1i = (const float*)d_in[3];
    const float* ur  = (const float*)d_in[4];
    const float* ui  = (const float*)d_in[5];

    cudaFuncSetAttribute(pass1_kernel, cudaFuncAttributeMaxDynamicSharedMemorySize, 65536);
    cudaFuncSetAttribute(pass2_kernel, cudaFuncAttributeMaxDynamicSharedMemorySize, 65536);

    pass1_kernel<<<2048, 512, 65536>>>(c0r, c0i, ur, ui);
    pass2_kernel<<<2048, 512, 65536>>>(c1r, c1i, ur, ui);
    pass3_kernel<<<1, 256>>>((float*)d_out);
}

// round 4
// speedup vs baseline: 1.0846x; 1.0846x over previous
#include <cuda_runtime.h>

// ---------------------------------------------------------------------------
// QECCEqualModel: 23-qubit statevector gate application + overlap loss.
// FMA-bound => packed fp32x2 complex math (fma.rn.f32x2), amplitudes carried
// as packed (re,im) 64-bit values through all gates.
//
// pass1: gates on state bits 0..12  (ind0 22..10), contiguous tiles -> scratch
// pass2: gates on state bits 13..22 (ind0 9..0), gathered tiles, fused dot
// pass3: deterministic reduction -> loss
// ---------------------------------------------------------------------------

#define DIMQ (1u << 23)
typedef unsigned long long u64c;

__device__ u64c  g_scratch[2u * DIMQ];     // 128 MB static scratch
__device__ float g_partials[2048 * 4];     // per-block overlap partials

__device__ __forceinline__ u64c pk(float x, float y) {
    u64c r; asm("mov.b64 %0,{%1,%2};" : "=l"(r) : "f"(x), "f"(y)); return r;
}
__device__ __forceinline__ void upk(u64c a, float& x, float& y) {
    asm("mov.b64 {%0,%1},%2;" : "=f"(x), "=f"(y) : "l"(a));
}
__device__ __forceinline__ u64c fma2(u64c a, u64c b, u64c c) {
    u64c r; asm("fma.rn.f32x2 %0,%1,%2,%3;" : "=l"(r) : "l"(a), "l"(b), "l"(c)); return r;
}
__device__ __forceinline__ u64c mul2(u64c a, u64c b) {
    u64c r; asm("mul.rn.f32x2 %0,%1,%2;" : "=l"(r) : "l"(a), "l"(b)); return r;
}
__device__ __forceinline__ u64c cswap(u64c a) {
    float x, y; upk(a, x, y); return pk(y, x);
}

// Packed gate constants, 8 per gate (u64 each), order:
//  [0]=(c00r,c00r) [1]=(-c00i,c00i) [2]=(c10r,c10r) [3]=(-c10i,c10i)
//  [4]=(c01r,c01r) [5]=(-c01i,c01i) [6]=(c11r,c11r) [7]=(-c11i,c11i)
// Complex MAC: acc += A*g_even + swap(A)*g_odd.
__device__ __forceinline__ void fill_gpk(u64c* gpk, const float* __restrict__ ur,
                                         const float* __restrict__ ui, int tid)
{
    if (tid < 184) {
        int gq = tid >> 3, k = tid & 7;
        int m = k >> 1;                                   // 0:c00 1:c10 2:c01 3:c11
        int off = (m == 0) ? 0 : (m == 1) ? 2 : (m == 2) ? 1 : 3;
        float vr = ur[gq * 4 + off], vi = ui[gq * 4 + off];
        gpk[tid] = (k & 1) ? pk(-vi, vi) : pk(vr, vr);
    }
}

// Gate across a register bit rb on 16 packed amplitudes.
__device__ __forceinline__ void reg_gate_p(u64c (&a)[16], int rb,
                                           const u64c* __restrict__ g)
{
    u64c g0 = g[0], g1 = g[1], g2 = g[2], g3 = g[3];
    u64c g4 = g[4], g5 = g[5], g6 = g[6], g7 = g[7];
#pragma unroll
    for (int r0 = 0; r0 < 16; ++r0) {
        if (r0 & (1 << rb)) continue;
        int r1 = r0 | (1 << rb);
        u64c A0 = a[r0], A1 = a[r1];
        u64c S0 = cswap(A0), S1 = cswap(A1);
        u64c o0 = mul2(A0, g0);
        o0 = fma2(S0, g1, o0); o0 = fma2(A1, g2, o0); o0 = fma2(S1, g3, o0);
        u64c o1 = mul2(A0, g4);
        o1 = fma2(S0, g5, o1); o1 = fma2(A1, g6, o1); o1 = fma2(S1, g7, o1);
        a[r0] = o0; a[r1] = o1;
    }
}

// Gate across a lane bit via shfl_xor; myb = my bit value.
// myb==0: new = me*c00 + other*c10 ; myb==1: new = other*c01 + me*c11
__device__ __forceinline__ void lane_gate_p(u64c (&a)[16], int mask, int myb,
                                            const u64c* __restrict__ g)
{
    u64c bcm = myb ? g[6] : g[0];   // (cm_r, cm_r)
    u64c ncm = myb ? g[7] : g[1];   // (-cm_i, cm_i)
    u64c bco = myb ? g[4] : g[2];   // (co_r, co_r)
    u64c nco = myb ? g[5] : g[3];   // (-co_i, co_i)
#pragma unroll
    for (int r = 0; r < 16; ++r) {
        float mx, my; upk(a[r], mx, my);
        float ox = __shfl_xor_sync(0xffffffffu, mx, mask);
        float oy = __shfl_xor_sync(0xffffffffu, my, mask);
        u64c res = mul2(a[r], bcm);
        res = fma2(pk(my, mx), ncm, res);
        res = fma2(pk(ox, oy), bco, res);
        res = fma2(pk(oy, ox), nco, res);
        a[r] = res;
    }
}

// ---------------------------------------------------------------------------
// Pass 1: contiguous tiles of 8192 amps; 512 threads x 16 packed amps.
// mapping1: t1=(r<<9)|(w<<5)|lane: lane bits 0..4 (ind0 22..18),
//           reg bits 9..12 (ind0 13..10)
// restage -> mapping2: t2=(w<<9)|(r<<5)|lane: reg bits 5..8 (ind0 17..14)
// ---------------------------------------------------------------------------
__global__ void __launch_bounds__(512, 2)
pass1_kernel(const float* __restrict__ c0r, const float* __restrict__ c0i,
             const float* __restrict__ ur,  const float* __restrict__ ui)
{
    __shared__ u64c gpk[184];
    extern __shared__ u64c sm[];   // 8192 u64 = 64 KB

    const int tid = threadIdx.x;
    fill_gpk(gpk, ur, ui, tid);
    __syncthreads();

    const int lane = tid & 31;
    const int w    = tid >> 5;
    const unsigned base = blockIdx.x * 8192u;

    u64c a[16];
#pragma unroll
    for (int r = 0; r < 16; ++r) {
        unsigned t1 = (unsigned)(r << 9) | (w << 5) | lane;
        a[r] = pk(__ldg(&c0r[base + t1]), __ldg(&c0i[base + t1]));
    }

#pragma unroll
    for (int j = 0; j < 5; ++j)
        lane_gate_p(a, 1 << j, (lane >> j) & 1, gpk + (22 - j) * 8);

#pragma unroll
    for (int rb = 0; rb < 4; ++rb)
        reg_gate_p(a, rb, gpk + (13 - rb) * 8);

#pragma unroll
    for (int r = 0; r < 16; ++r)
        sm[(unsigned)(r << 9) | (w << 5) | lane] = a[r];
    __syncthreads();
#pragma unroll
    for (int r = 0; r < 16; ++r)
        a[r] = sm[(unsigned)(w << 9) | (r << 5) | lane];

#pragma unroll
    for (int rb = 0; rb < 4; ++rb)
        reg_gate_p(a, rb, gpk + (17 - rb) * 8);

#pragma unroll
    for (int r = 0; r < 16; ++r)
        g_scratch[base + ((unsigned)(w << 9) | (r << 5) | lane)] = a[r];
}

// ---------------------------------------------------------------------------
// Pass 2: gathered tiles (2^10 high-bit combos x 8 contiguous), fused dot.
// tile bit j>=3 = state bit 10+j -> ind0 = 12-j.
//   lane gates: tile bits 3,4 -> ind0 9,8
//   reg gates m1: tile bits 9..12 -> ind0 3..0
//   restage; reg gates m2: tile bits 5..8 -> ind0 7..4
// ---------------------------------------------------------------------------
__global__ void __launch_bounds__(512, 2)
pass2_kernel(const float* __restrict__ c1r, const float* __restrict__ c1i,
             const float* __restrict__ ur,  const float* __restrict__ ui)
{
    __shared__ u64c gpk[184];
    extern __shared__ u64c sm[];

    const int tid = threadIdx.x;
    fill_gpk(gpk, ur, ui, tid);
    __syncthreads();

    const int lane = tid & 31;
    const int w    = tid >> 5;
    const unsigned b  = blockIdx.x;
    const unsigned p  = b >> 10;
    const unsigned l0 = (b & 1023u) * 8u;
    const unsigned stateBase = p << 23;

    u64c a[16];
#pragma unroll
    for (int r = 0; r < 16; ++r) {
        unsigned t1 = (unsigned)(r << 9) | (w << 5) | lane;
        unsigned s  = ((t1 >> 3) << 13) + l0 + (t1 & 7u);
        a[r] = g_scratch[stateBase + s];
    }

    lane_gate_p(a, 1 << 3, (lane >> 3) & 1, gpk + 9 * 8);
    lane_gate_p(a, 1 << 4, (lane >> 4) & 1, gpk + 8 * 8);

#pragma unroll
    for (int rb = 0; rb < 4; ++rb)
        reg_gate_p(a, rb, gpk + (3 - rb) * 8);

#pragma unroll
    for (int r = 0; r < 16; ++r)
        sm[(unsigned)(r << 9) | (w << 5) | lane] = a[r];
    __syncthreads();
#pragma unroll
    for (int r = 0; r < 16; ++r)
        a[r] = sm[(unsigned)(w << 9) | (r << 5) | lane];

#pragma unroll
    for (int rb = 0; rb < 4; ++rb)
        reg_gate_p(a, rb, gpk + (7 - rb) * 8);

    // fused dot: accA=(acc0,-acc1), accB=(acc2,-acc3)
    //   acc0 += dr*xr + di*xi ; -acc1 += di*xr - dr*xi
    //   => accA += D*bc(xr) + (di,-dr)*bc(xi)
    u64c accA = 0ull, accB = 0ull;
#pragma unroll
    for (int r = 0; r < 16; ++r) {
        unsigned t2 = (unsigned)(w << 9) | (r << 5) | lane;
        unsigned s  = ((t2 >> 3) << 13) + l0 + (t2 & 7u);
        float dr, di; upk(a[r], dr, di);
        u64c D  = a[r];
        u64c ND = pk(di, -dr);
        float xr = __ldg(&c1r[s]),        xi = __ldg(&c1i[s]);
        accA = fma2(D,  pk(xr, xr), accA);
        accA = fma2(ND, pk(xi, xi), accA);
        float yr = __ldg(&c1r[DIMQ + s]), yi = __ldg(&c1i[DIMQ + s]);
        accB = fma2(D,  pk(yr, yr), accB);
        accB = fma2(ND, pk(yi, yi), accB);
    }
    float acc0, acc1m, acc2, acc3m;
    upk(accA, acc0, acc1m); upk(accB, acc2, acc3m);
    float acc1 = -acc1m, acc3 = -acc3m;

    // deterministic block reduction
#pragma unroll
    for (int o = 16; o > 0; o >>= 1) {
        acc0 += __shfl_xor_sync(0xffffffffu, acc0, o);
        acc1 += __shfl_xor_sync(0xffffffffu, acc1, o);
        acc2 += __shfl_xor_sync(0xffffffffu, acc2, o);
        acc3 += __shfl_xor_sync(0xffffffffu, acc3, o);
    }
    __syncthreads();
    float* red = (float*)sm;          // 16 warps x 4 floats
    if (lane == 0) {
        red[w*4+0] = acc0; red[w*4+1] = acc1;
        red[w*4+2] = acc2; red[w*4+3] = acc3;
    }
    __syncthreads();
    if (tid < 4) {
        float s = 0.f;
#pragma unroll
        for (int k = 0; k < 16; ++k) s += red[k*4 + tid];
        g_partials[b*4 + tid] = s;
    }
}

// ---------------------------------------------------------------------------
// Pass 3: fixed-order reduction of 2048 block partials -> loss scalar.
// ---------------------------------------------------------------------------
__global__ void pass3_kernel(float* __restrict__ out)
{
    __shared__ float sred[256][8];
    const int tid = threadIdx.x;
    float acc[8];
#pragma unroll
    for (int j = 0; j < 8; ++j) acc[j] = 0.f;

    for (int t = tid; t < 1024; t += 256) {
#pragma unroll
        for (int pq = 0; pq < 2; ++pq)
#pragma unroll
            for (int j = 0; j < 4; ++j)
                acc[pq*4 + j] += g_partials[(pq*1024 + t)*4 + j];
    }
#pragma unroll
    for (int j = 0; j < 8; ++j) sred[tid][j] = acc[j];
    __syncthreads();
    for (int off = 128; off > 0; off >>= 1) {
        if (tid < off) {
#pragma unroll
            for (int j = 0; j < 8; ++j) sred[tid][j] += sred[tid + off][j];
        }
        __syncthreads();
    }
    if (tid == 0) {
        float s = 0.f;
#pragma unroll
        for (int j = 0; j < 8; ++j) s += sred[0][j] * sred[0][j];
        out[0] = 2.0f - s;
    }
}

// ---------------------------------------------------------------------------
extern "C" void kernel_launch(void* const* d_in, const int* in_sizes, int n_in,
                              void* d_out, int out_size)
{
    (void)in_sizes; (void)n_in; (void)out_size;
    const float* c0r = (const float*)d_in[0];
    const float* c0i = (const float*)d_in[1];
    const float* c1r = (const float*)d_in[2];
    const float* c1i = (const float*)d_in[3];
    const float* ur  = (const float*)d_in[4];
    const float* ui  = (const float*)d_in[5];

    cudaFuncSetAttribute(pass1_kernel, cudaFuncAttributeMaxDynamicSharedMemorySize, 65536);
    cudaFuncSetAttribute(pass2_kernel, cudaFuncAttributeMaxDynamicSharedMemorySize, 65536);

    pass1_kernel<<<2048, 512, 65536>>>(c0r, c0i, ur, ui);
    pass2_kernel<<<2048, 512, 65536>>>(c1r, c1i, ur, ui);
    pass3_kernel<<<1, 256>>>((float*)d_out);
}

// round 5
// speedup vs baseline: 1.2634x; 1.1649x over previous
#include <cuda_runtime.h>
#include <math.h>

// ---------------------------------------------------------------------------
// QECCEqualModel via Givens decomposition:
//   each gate M_k = D1_k * G_k(theta) * D2_k  (diag * real rotation * diag)
//   all D2 -> single per-amp pre-phase at pass1 load
//   all G  -> real Givens (half the FMA count of complex 2x2)
//   all D1 -> single per-amp post-phase folded into pass2's dot
//   global phase dropped (loss uses |overlap|^2)
// pass1: G on state bits 0..12, contiguous tiles -> scratch
// pass2: G on state bits 13..22, gathered tiles + post-phase + fused dot
// ---------------------------------------------------------------------------

#define DIMQ (1u << 23)
typedef unsigned long long u64c;

__device__ u64c  g_scratch[2u * DIMQ];
__device__ float g_partials[2048 * 4];
__device__ float g_gc[23], g_gs[23], g_pre[23], g_post[23];  // per state bit j

__device__ __forceinline__ u64c pk(float x, float y) {
    u64c r; asm("mov.b64 %0,{%1,%2};" : "=l"(r) : "f"(x), "f"(y)); return r;
}
__device__ __forceinline__ void upk(u64c a, float& x, float& y) {
    asm("mov.b64 {%0,%1},%2;" : "=f"(x), "=f"(y) : "l"(a));
}
__device__ __forceinline__ u64c fma2(u64c a, u64c b, u64c c) {
    u64c r; asm("fma.rn.f32x2 %0,%1,%2,%3;" : "=l"(r) : "l"(a), "l"(b), "l"(c)); return r;
}
__device__ __forceinline__ u64c mul2(u64c a, u64c b) {
    u64c r; asm("mul.rn.f32x2 %0,%1,%2;" : "=l"(r) : "l"(a), "l"(b)); return r;
}

// ---------------------------------------------------------------------------
// Setup: decompose M_k = U_k^T = D1*G*D2 for each gate; store per state bit.
// M = [[c e^{ia}, -s e^{i(a+d)}],[s e^{ib}, c e^{i(b+d)}]]
//   c=|m00|, s=|m10|, a=arg(m00), b=arg(m10), d=arg(-m01)-a (or arg(m11)-b)
// pre[j]=d (bit=1 phase before G), post[j]=b-a (bit=1 phase after G).
// ---------------------------------------------------------------------------
__global__ void setup_kernel(const float* __restrict__ ur,
                             const float* __restrict__ ui)
{
    int k = threadIdx.x;
    if (k >= 23) return;
    // M = U^T: m00=u00, m01=u10, m10=u01, m11=u11
    float m00r = ur[k*4+0], m00i = ui[k*4+0];
    float m01r = ur[k*4+2], m01i = ui[k*4+2];
    float m10r = ur[k*4+1], m10i = ui[k*4+1];
    float m11r = ur[k*4+3], m11i = ui[k*4+3];
    float c = sqrtf(m00r*m00r + m00i*m00i);
    float s = sqrtf(m10r*m10r + m10i*m10i);
    const float eps = 1e-20f;
    float a = (c > eps) ? atan2f(m00i, m00r) : 0.0f;
    float b = (s > eps) ? atan2f(m10i, m10r) : 0.0f;
    float d = (s > eps) ? (atan2f(-m01i, -m01r) - a)
                        : (atan2f(m11i, m11r) - b);
    int j = 22 - k;        // gate k acts on state bit 22-k
    g_gc[j] = c; g_gs[j] = s;
    g_pre[j] = d; g_post[j] = b - a;
}

// Real Givens across a register bit rb: o0 = c*A0 - s*A1 ; o1 = s*A0 + c*A1
__device__ __forceinline__ void reg_gate_r(u64c (&a)[16], int rb, float c, float s)
{
    u64c cc = pk(c, c), ss = pk(s, s), ns = pk(-s, -s);
#pragma unroll
    for (int r0 = 0; r0 < 16; ++r0) {
        if (r0 & (1 << rb)) continue;
        int r1 = r0 | (1 << rb);
        u64c A0 = a[r0], A1 = a[r1];
        a[r0] = fma2(A1, ns, mul2(A0, cc));
        a[r1] = fma2(A1, cc, mul2(A0, ss));
    }
}

// Real Givens across a lane bit: new = c*me + t*other, t = myb ? s : -s
__device__ __forceinline__ void lane_gate_r(u64c (&a)[16], int mask, int myb,
                                            float c, float s)
{
    float t = myb ? s : -s;
    u64c cc = pk(c, c), tt = pk(t, t);
#pragma unroll
    for (int r = 0; r < 16; ++r) {
        float mx, my; upk(a[r], mx, my);
        float ox = __shfl_xor_sync(0xffffffffu, mx, mask);
        float oy = __shfl_xor_sync(0xffffffffu, my, mask);
        a[r] = fma2(pk(ox, oy), tt, mul2(a[r], cc));
    }
}

// ---------------------------------------------------------------------------
// Pass 1: contiguous tiles of 8192 amps. mapping1 t1=(r<<9)|(w<<5)|lane:
// lane bits = state 0..4, warp = 5..8, reg = 9..12. Restage swaps r<->w.
// Pre-phase over ALL 23 bits applied at load.
// ---------------------------------------------------------------------------
__global__ void __launch_bounds__(512, 2)
pass1_kernel(const float* __restrict__ c0r, const float* __restrict__ c0i)
{
    extern __shared__ u64c sm[];   // 8192 u64 = 64 KB restage buffer

    const int tid  = threadIdx.x;
    const int lane = tid & 31;
    const int w    = tid >> 5;
    const unsigned bid  = blockIdx.x;
    const unsigned base = bid * 8192u;

    // per-thread fixed part of the pre-phase angle
    float th = 0.0f;
#pragma unroll
    for (int m = 0; m < 10; ++m)
        th += (float)((bid >> m) & 1u) * __ldg(&g_pre[13 + m]);
#pragma unroll
    for (int j = 0; j < 5; ++j)
        th += (float)((lane >> j) & 1) * __ldg(&g_pre[j]);
#pragma unroll
    for (int m = 0; m < 4; ++m)
        th += (float)((w >> m) & 1) * __ldg(&g_pre[5 + m]);
    const float p9  = __ldg(&g_pre[9]),  p10 = __ldg(&g_pre[10]);
    const float p11 = __ldg(&g_pre[11]), p12 = __ldg(&g_pre[12]);

    u64c a[16];
#pragma unroll
    for (int r = 0; r < 16; ++r) {
        unsigned t1 = (unsigned)(r << 9) | (w << 5) | lane;
        float xr = __ldg(&c0r[base + t1]);
        float xi = __ldg(&c0i[base + t1]);
        float thr = th;
        if (r & 1) thr += p9;
        if (r & 2) thr += p10;
        if (r & 4) thr += p11;
        if (r & 8) thr += p12;
        float sn, cs; __sincosf(thr, &sn, &cs);
        // (xr*cs - xi*sn, xi*cs + xr*sn)
        a[r] = fma2(pk(xi, xr), pk(-sn, sn), mul2(pk(xr, xi), pk(cs, cs)));
    }

    // lane gates: state bits 0..4
#pragma unroll
    for (int j = 0; j < 5; ++j)
        lane_gate_r(a, 1 << j, (lane >> j) & 1, __ldg(&g_gc[j]), __ldg(&g_gs[j]));

    // reg gates m1: state bits 9..12
#pragma unroll
    for (int rb = 0; rb < 4; ++rb)
        reg_gate_r(a, rb, __ldg(&g_gc[9 + rb]), __ldg(&g_gs[9 + rb]));

    // restage: swap reg bits <-> warp bits
#pragma unroll
    for (int r = 0; r < 16; ++r)
        sm[(unsigned)(r << 9) | (w << 5) | lane] = a[r];
    __syncthreads();
#pragma unroll
    for (int r = 0; r < 16; ++r)
        a[r] = sm[(unsigned)(w << 9) | (r << 5) | lane];

    // reg gates m2: state bits 5..8
#pragma unroll
    for (int rb = 0; rb < 4; ++rb)
        reg_gate_r(a, rb, __ldg(&g_gc[5 + rb]), __ldg(&g_gs[5 + rb]));

#pragma unroll
    for (int r = 0; r < 16; ++r)
        g_scratch[base + ((unsigned)(w << 9) | (r << 5) | lane)] = a[r];
}

// ---------------------------------------------------------------------------
// Pass 2: gathered tiles (2^10 high combos x 8 contiguous low), post-phase,
// fused dot. tile bit j>=3 = state bit 10+j.
//   lane gates: tile bits 3,4 -> state 13,14
//   reg m1: tile bits 9..12 -> state 19..22
//   restage; reg m2: tile bits 5..8 -> state 15..18
// post mapping m2: t2=(w<<9)|(r<<5)|lane:
//   state 0..2 = lane bits 0..2; state 3..12 = blockIdx bits 0..9;
//   state 13,14 = lane bits 3,4; state 15..18 = r; state 19..22 = w.
// ---------------------------------------------------------------------------
__global__ void __launch_bounds__(512, 2)
pass2_kernel(const float* __restrict__ c1r, const float* __restrict__ c1i)
{
    extern __shared__ u64c sm[];

    const int tid  = threadIdx.x;
    const int lane = tid & 31;
    const int w    = tid >> 5;
    const unsigned b  = blockIdx.x;
    const unsigned p  = b >> 10;
    const unsigned l0 = (b & 1023u) * 8u;
    const unsigned stateBase = p << 23;

    u64c a[16];
#pragma unroll
    for (int r = 0; r < 16; ++r) {
        unsigned t1 = (unsigned)(r << 9) | (w << 5) | lane;
        unsigned s  = ((t1 >> 3) << 13) + l0 + (t1 & 7u);
        a[r] = g_scratch[stateBase + s];
    }

    // lane gates: state bits 13,14 (tile bits 3,4)
    lane_gate_r(a, 1 << 3, (lane >> 3) & 1, __ldg(&g_gc[13]), __ldg(&g_gs[13]));
    lane_gate_r(a, 1 << 4, (lane >> 4) & 1, __ldg(&g_gc[14]), __ldg(&g_gs[14]));

    // reg gates m1: state bits 19..22
#pragma unroll
    for (int rb = 0; rb < 4; ++rb)
        reg_gate_r(a, rb, __ldg(&g_gc[19 + rb]), __ldg(&g_gs[19 + rb]));

#pragma unroll
    for (int r = 0; r < 16; ++r)
        sm[(unsigned)(r << 9) | (w << 5) | lane] = a[r];
    __syncthreads();
#pragma unroll
    for (int r = 0; r < 16; ++r)
        a[r] = sm[(unsigned)(w << 9) | (r << 5) | lane];

    // reg gates m2: state bits 15..18
#pragma unroll
    for (int rb = 0; rb < 4; ++rb)
        reg_gate_r(a, rb, __ldg(&g_gc[15 + rb]), __ldg(&g_gs[15 + rb]));

    // post-phase fixed part (mapping m2)
    float th = 0.0f;
#pragma unroll
    for (int j = 0; j < 3; ++j)
        th += (float)((lane >> j) & 1) * __ldg(&g_post[j]);
#pragma unroll
    for (int m = 0; m < 10; ++m)
        th += (float)((b >> m) & 1u) * __ldg(&g_post[3 + m]);
    th += (float)((lane >> 3) & 1) * __ldg(&g_post[13]);
    th += (float)((lane >> 4) & 1) * __ldg(&g_post[14]);
#pragma unroll
    for (int m = 0; m < 4; ++m)
        th += (float)((w >> m) & 1) * __ldg(&g_post[19 + m]);
    const float q15 = __ldg(&g_post[15]), q16 = __ldg(&g_post[16]);
    const float q17 = __ldg(&g_post[17]), q18 = __ldg(&g_post[18]);

    // post-phase + fused dot: accA=(acc0,-acc1), accB=(acc2,-acc3)
    u64c accA = 0ull, accB = 0ull;
#pragma unroll
    for (int r = 0; r < 16; ++r) {
        unsigned t2 = (unsigned)(w << 9) | (r << 5) | lane;
        unsigned s  = ((t2 >> 3) << 13) + l0 + (t2 & 7u);
        float thr = th;
        if (r & 1) thr += q15;
        if (r & 2) thr += q16;
        if (r & 4) thr += q17;
        if (r & 8) thr += q18;
        float sn, cs; __sincosf(thr, &sn, &cs);
        float vr, vi; upk(a[r], vr, vi);
        float er = vr*cs - vi*sn;
        float ei = vi*cs + vr*sn;
        u64c D  = pk(er, ei);
        u64c ND = pk(ei, -er);
        float xr = __ldg(&c1r[s]),        xi = __ldg(&c1i[s]);
        accA = fma2(D,  pk(xr, xr), accA);
        accA = fma2(ND, pk(xi, xi), accA);
        float yr = __ldg(&c1r[DIMQ + s]), yi = __ldg(&c1i[DIMQ + s]);
        accB = fma2(D,  pk(yr, yr), accB);
        accB = fma2(ND, pk(yi, yi), accB);
    }
    float acc0, acc1m, acc2, acc3m;
    upk(accA, acc0, acc1m); upk(accB, acc2, acc3m);
    float acc1 = -acc1m, acc3 = -acc3m;

#pragma unroll
    for (int o = 16; o > 0; o >>= 1) {
        acc0 += __shfl_xor_sync(0xffffffffu, acc0, o);
        acc1 += __shfl_xor_sync(0xffffffffu, acc1, o);
        acc2 += __shfl_xor_sync(0xffffffffu, acc2, o);
        acc3 += __shfl_xor_sync(0xffffffffu, acc3, o);
    }
    __syncthreads();
    float* red = (float*)sm;
    if (lane == 0) {
        red[w*4+0] = acc0; red[w*4+1] = acc1;
        red[w*4+2] = acc2; red[w*4+3] = acc3;
    }
    __syncthreads();
    if (tid < 4) {
        float s = 0.f;
#pragma unroll
        for (int k = 0; k < 16; ++k) s += red[k*4 + tid];
        g_partials[b*4 + tid] = s;
    }
}

// ---------------------------------------------------------------------------
__global__ void pass3_kernel(float* __restrict__ out)
{
    __shared__ float sred[256][8];
    const int tid = threadIdx.x;
    float acc[8];
#pragma unroll
    for (int j = 0; j < 8; ++j) acc[j] = 0.f;

    for (int t = tid; t < 1024; t += 256) {
#pragma unroll
        for (int pq = 0; pq < 2; ++pq)
#pragma unroll
            for (int j = 0; j < 4; ++j)
                acc[pq*4 + j] += g_partials[(pq*1024 + t)*4 + j];
    }
#pragma unroll
    for (int j = 0; j < 8; ++j) sred[tid][j] = acc[j];
    __syncthreads();
    for (int off = 128; off > 0; off >>= 1) {
        if (tid < off) {
#pragma unroll
            for (int j = 0; j < 8; ++j) sred[tid][j] += sred[tid + off][j];
        }
        __syncthreads();
    }
    if (tid == 0) {
        float s = 0.f;
#pragma unroll
        for (int j = 0; j < 8; ++j) s += sred[0][j] * sred[0][j];
        out[0] = 2.0f - s;
    }
}

// ---------------------------------------------------------------------------
extern "C" void kernel_launch(void* const* d_in, const int* in_sizes, int n_in,
                              void* d_out, int out_size)
{
    (void)in_sizes; (void)n_in; (void)out_size;
    const float* c0r = (const float*)d_in[0];
    const float* c0i = (const float*)d_in[1];
    const float* c1r = (const float*)d_in[2];
    const float* c1i = (const float*)d_in[3];
    const float* ur  = (const float*)d_in[4];
    const float* ui  = (const float*)d_in[5];

    cudaFuncSetAttribute(pass1_kernel, cudaFuncAttributeMaxDynamicSharedMemorySize, 65536);
    cudaFuncSetAttribute(pass2_kernel, cudaFuncAttributeMaxDynamicSharedMemorySize, 65536);

    setup_kernel<<<1, 32>>>(ur, ui);
    pass1_kernel<<<2048, 512, 65536>>>(c0r, c0i);
    pass2_kernel<<<2048, 512, 65536>>>(c1r, c1i);
    pass3_kernel<<<1, 256>>>((float*)d_out);
}